// round 10
// baseline (speedup 1.0000x reference)
#include <cuda_runtime.h>

#define N_NODES 50000
#define N_EDGES 800000
#define IN_CH 128
#define HID 64

#define SB 512
#define NSB ((N_NODES + SB - 1) / SB)   // 98

// ---------------- scratch (static device globals: allocation-free) ----------
__device__ int   g_deg[N_NODES];
__device__ int   g_off[N_NODES];
__device__ int   g_woff[N_NODES];
__device__ int   g_csr[N_EDGES];
__device__ float g_y2[N_NODES * 128];   // layer1: cols 0:64 = x@w1l, 64:128 = x@w1r
__device__ float g_y2b[N_NODES * 128];  // layer2: cols 0:64 = h@w2l, 64:128 = h@w2r

// ---------------- f32x2 helpers ---------------------------------------------
__device__ __forceinline__ void fma2(unsigned long long& d,
                                     unsigned long long a,
                                     unsigned long long b) {
    asm("fma.rn.f32x2 %0, %1, %2, %0;" : "+l"(d) : "l"(a), "l"(b));
}
__device__ __forceinline__ float2 u2f(unsigned long long v) {
    float2 r;
    asm("mov.b64 {%0, %1}, %2;" : "=f"(r.x), "=f"(r.y) : "l"(v));
    return r;
}

// ---------------- CSR build --------------------------------------------------
__global__ void zero_deg_kernel() {
    int i = blockIdx.x * blockDim.x + threadIdx.x;
    if (i < N_NODES) g_deg[i] = 0;
}

__global__ void hist_kernel(const int* __restrict__ dst) {
    int e = blockIdx.x * blockDim.x + threadIdx.x;
    if (e < N_EDGES) atomicAdd(&g_deg[dst[e]], 1);
}

// single-block full exclusive scan of g_deg -> g_off, g_woff
#define SCAN_T 1024
__global__ void __launch_bounds__(SCAN_T) scan_all_kernel() {
    __shared__ int warpsum[32];
    int t = threadIdx.x;
    int lane = t & 31, wid = t >> 5;
    const int CH = (N_NODES + SCAN_T - 1) / SCAN_T;   // 49
    int lo = t * CH;
    int hi = min(lo + CH, N_NODES);

    int local = 0;
    for (int i = lo; i < hi; i++) local += g_deg[i];

    // warp inclusive scan
    int v = local;
    #pragma unroll
    for (int d = 1; d < 32; d <<= 1) {
        int u = __shfl_up_sync(0xffffffffu, v, d);
        if (lane >= d) v += u;
    }
    if (lane == 31) warpsum[wid] = v;
    __syncthreads();
    if (wid == 0) {
        int w = warpsum[lane];
        #pragma unroll
        for (int d = 1; d < 32; d <<= 1) {
            int u = __shfl_up_sync(0xffffffffu, w, d);
            if (lane >= d) w += u;
        }
        warpsum[lane] = w;
    }
    __syncthreads();

    int base = (v - local) + (wid ? warpsum[wid - 1] : 0);  // thread-exclusive prefix
    for (int i = lo; i < hi; i++) {
        g_off[i] = base;
        g_woff[i] = base;
        base += g_deg[i];
    }
}

__global__ void fill_kernel(const int* __restrict__ src,
                            const int* __restrict__ dst) {
    int e = blockIdx.x * blockDim.x + threadIdx.x;
    if (e < N_EDGES) {
        int pos = atomicAdd(&g_woff[dst[e]], 1);
        g_csr[pos] = src[e];
    }
}

// ---------------- layer-1 GEMM: g_y2[N,128] = x[N,128] @ [Wl | Wr] ----------
// (same validated structure as R9)
__global__ void __launch_bounds__(256) gemm1_kernel(const float* __restrict__ A,
                                                    const float* __restrict__ Wl,
                                                    const float* __restrict__ Wr) {
    __shared__ float Ws[64][128];
    __shared__ float Asd[16][136];

    int tid = threadIdx.x;
    int tx = tid & 15;
    int ty = tid >> 4;
    int rbase = blockIdx.x * 64;

    unsigned long long acc[4][4] = {};
    int ar = tid >> 2;
    int ak4 = (tid & 3) << 2;

    for (int kc = 0; kc < IN_CH; kc += 64) {
        for (int ks = 0; ks < 64; ks += 16) {
            if (ks == 0) {
                #pragma unroll
                for (int i = 0; i < 8; i++) {
                    int li = tid + i * 256;
                    int wk = li >> 5;
                    int wc4 = (li & 31) << 2;
                    const float* srcp = (wc4 < 64)
                        ? (Wl + (size_t)(kc + wk) * 64 + wc4)
                        : (Wr + (size_t)(kc + wk) * 64 + (wc4 - 64));
                    *(float4*)&Ws[wk][wc4] = *(const float4*)srcp;
                }
            }
            {
                int gr = rbase + ar;
                float4 a = make_float4(0.f, 0.f, 0.f, 0.f);
                if (gr < N_NODES)
                    a = *(const float4*)(A + (size_t)gr * IN_CH + kc + ks + ak4);
                *(float2*)&Asd[ak4 + 0][2 * ar] = make_float2(a.x, a.x);
                *(float2*)&Asd[ak4 + 1][2 * ar] = make_float2(a.y, a.y);
                *(float2*)&Asd[ak4 + 2][2 * ar] = make_float2(a.z, a.z);
                *(float2*)&Asd[ak4 + 3][2 * ar] = make_float2(a.w, a.w);
            }
            __syncthreads();

            #pragma unroll
            for (int k = 0; k < 16; k++) {
                ulonglong2 a01 = *(const ulonglong2*)&Asd[k][ty * 8];
                ulonglong2 a23 = *(const ulonglong2*)&Asd[k][ty * 8 + 4];
                ulonglong2 w01 = *(const ulonglong2*)&Ws[ks + k][tx * 4];
                ulonglong2 w23 = *(const ulonglong2*)&Ws[ks + k][64 + tx * 4];
                fma2(acc[0][0], a01.x, w01.x); fma2(acc[0][1], a01.x, w01.y);
                fma2(acc[0][2], a01.x, w23.x); fma2(acc[0][3], a01.x, w23.y);
                fma2(acc[1][0], a01.y, w01.x); fma2(acc[1][1], a01.y, w01.y);
                fma2(acc[1][2], a01.y, w23.x); fma2(acc[1][3], a01.y, w23.y);
                fma2(acc[2][0], a23.x, w01.x); fma2(acc[2][1], a23.x, w01.y);
                fma2(acc[2][2], a23.x, w23.x); fma2(acc[2][3], a23.x, w23.y);
                fma2(acc[3][0], a23.y, w01.x); fma2(acc[3][1], a23.y, w01.y);
                fma2(acc[3][2], a23.y, w23.x); fma2(acc[3][3], a23.y, w23.y);
            }
            __syncthreads();
        }
    }

    #pragma unroll
    for (int i = 0; i < 4; i++) {
        int r = rbase + ty * 4 + i;
        if (r >= N_NODES) continue;
        float2 p0 = u2f(acc[i][0]);
        float2 p1 = u2f(acc[i][1]);
        float2 p2 = u2f(acc[i][2]);
        float2 p3 = u2f(acc[i][3]);
        *(float4*)(g_y2 + (size_t)r * 128 + tx * 4) =
            make_float4(p0.x, p0.y, p1.x, p1.y);
        *(float4*)(g_y2 + (size_t)r * 128 + 64 + tx * 4) =
            make_float4(p2.x, p2.y, p3.x, p3.y);
    }
}

// ---------------- fused gather1 + gemm2 -------------------------------------
// Block b owns rows [64b, 64b+64). Phase 1: each warp gathers 8 nodes
// (half-warp per edge, float4 lanes) and writes h = relu(mean@.. ) rows into
// smem Ah. Phase 2: K=64 GEMM from Ah against [w2l|w2r], writing g_y2b.
// Dynamic smem: Ws[64*128] + Ah[64*68] + Asd[16*136] = 57.5 KB.
__global__ void __launch_bounds__(256) fused_kernel(const float* __restrict__ y2,
                                                    const float* __restrict__ b1v,
                                                    const float* __restrict__ Wl,
                                                    const float* __restrict__ Wr,
                                                    float* __restrict__ y2b) {
    extern __shared__ float sm[];
    float* Ws  = sm;                 // [64][128]
    float* Ah  = sm + 64 * 128;      // [64][68]
    float* Asd = Ah + 64 * 68;       // [16][136]

    int tid = threadIdx.x;
    int lane = tid & 31;
    int warp = tid >> 5;
    int rbase = blockIdx.x * 64;

    // stage Ws for K=64 (once)
    #pragma unroll
    for (int i = 0; i < 8; i++) {
        int li = tid + i * 256;
        int wk = li >> 5;
        int wc4 = (li & 31) << 2;
        const float* srcp = (wc4 < 64)
            ? (Wl + (size_t)wk * 64 + wc4)
            : (Wr + (size_t)wk * 64 + (wc4 - 64));
        *(float4*)&Ws[wk * 128 + wc4] = *(const float4*)srcp;
    }

    // ---- phase 1: gather 8 nodes per warp into Ah ----
    int half = lane >> 4;
    int c4 = (lane & 15) << 2;
    const unsigned FULL = 0xffffffffu;

    for (int i = 0; i < 8; i++) {
        int gw = rbase + warp * 8 + i;
        if (gw >= N_NODES) break;   // uniform per warp

        int off = g_off[gw];
        int deg = g_deg[gw];

        float4 acc0 = make_float4(0.f, 0.f, 0.f, 0.f);
        float4 acc1 = make_float4(0.f, 0.f, 0.f, 0.f);

        for (int base = 0; base < deg; base += 32) {
            int n = min(32, deg - base);
            int sv = (lane < n) ? __ldg(&g_csr[off + base + lane]) : 0;
            int k = 0;
            for (; k + 4 <= n; k += 4) {
                int sa = __shfl_sync(FULL, sv, k + half);
                int sb = __shfl_sync(FULL, sv, k + 2 + half);
                float4 va = *(const float4*)(y2 + (size_t)sa * 128 + c4);
                float4 vb = *(const float4*)(y2 + (size_t)sb * 128 + c4);
                acc0.x += va.x; acc0.y += va.y; acc0.z += va.z; acc0.w += va.w;
                acc1.x += vb.x; acc1.y += vb.y; acc1.z += vb.z; acc1.w += vb.w;
            }
            if (k + 2 <= n) {
                int sa = __shfl_sync(FULL, sv, k + half);
                float4 va = *(const float4*)(y2 + (size_t)sa * 128 + c4);
                acc0.x += va.x; acc0.y += va.y; acc0.z += va.z; acc0.w += va.w;
                k += 2;
            }
            if (k < n) {
                int sa = __shfl_sync(FULL, sv, k);
                if (half == 0) {
                    float4 va = *(const float4*)(y2 + (size_t)sa * 128 + c4);
                    acc0.x += va.x; acc0.y += va.y; acc0.z += va.z; acc0.w += va.w;
                }
            }
        }

        float4 acc;
        acc.x = acc0.x + acc1.x;
        acc.y = acc0.y + acc1.y;
        acc.z = acc0.z + acc1.z;
        acc.w = acc0.w + acc1.w;
        acc.x += __shfl_down_sync(FULL, acc.x, 16);
        acc.y += __shfl_down_sync(FULL, acc.y, 16);
        acc.z += __shfl_down_sync(FULL, acc.z, 16);
        acc.w += __shfl_down_sync(FULL, acc.w, 16);

        if (half == 0) {
            float scale = 1.f / fmaxf((float)deg, 1.f);
            float4 z = *(const float4*)(y2 + (size_t)gw * 128 + 64 + c4);
            float4 b = *(const float4*)(b1v + c4);
            float4 o;
            o.x = fmaxf(fmaf(acc.x, scale, z.x) + b.x, 0.f);
            o.y = fmaxf(fmaf(acc.y, scale, z.y) + b.y, 0.f);
            o.z = fmaxf(fmaf(acc.z, scale, z.z) + b.z, 0.f);
            o.w = fmaxf(fmaf(acc.w, scale, z.w) + b.w, 0.f);
            *(float4*)&Ah[(warp * 8 + i) * 68 + c4] = o;
        }
    }
    __syncthreads();   // Ah + Ws visible to all

    // ---- phase 2: C[64,128] = Ah[64,64] @ Ws ----
    int tx = tid & 15;
    int ty = tid >> 4;
    unsigned long long acc[4][4] = {};
    int ar = tid >> 2;
    int ak4 = (tid & 3) << 2;

    for (int ks = 0; ks < 64; ks += 16) {
        float4 a = *(const float4*)&Ah[ar * 68 + ks + ak4];
        if (ks) __syncthreads();             // prior compute done before Asd overwrite
        *(float2*)&Asd[(ak4 + 0) * 136 + 2 * ar] = make_float2(a.x, a.x);
        *(float2*)&Asd[(ak4 + 1) * 136 + 2 * ar] = make_float2(a.y, a.y);
        *(float2*)&Asd[(ak4 + 2) * 136 + 2 * ar] = make_float2(a.z, a.z);
        *(float2*)&Asd[(ak4 + 3) * 136 + 2 * ar] = make_float2(a.w, a.w);
        __syncthreads();

        #pragma unroll
        for (int k = 0; k < 16; k++) {
            ulonglong2 a01 = *(const ulonglong2*)&Asd[k * 136 + ty * 8];
            ulonglong2 a23 = *(const ulonglong2*)&Asd[k * 136 + ty * 8 + 4];
            ulonglong2 w01 = *(const ulonglong2*)&Ws[(ks + k) * 128 + tx * 4];
            ulonglong2 w23 = *(const ulonglong2*)&Ws[(ks + k) * 128 + 64 + tx * 4];
            fma2(acc[0][0], a01.x, w01.x); fma2(acc[0][1], a01.x, w01.y);
            fma2(acc[0][2], a01.x, w23.x); fma2(acc[0][3], a01.x, w23.y);
            fma2(acc[1][0], a01.y, w01.x); fma2(acc[1][1], a01.y, w01.y);
            fma2(acc[1][2], a01.y, w23.x); fma2(acc[1][3], a01.y, w23.y);
            fma2(acc[2][0], a23.x, w01.x); fma2(acc[2][1], a23.x, w01.y);
            fma2(acc[2][2], a23.x, w23.x); fma2(acc[2][3], a23.x, w23.y);
            fma2(acc[3][0], a23.y, w01.x); fma2(acc[3][1], a23.y, w01.y);
            fma2(acc[3][2], a23.y, w23.x); fma2(acc[3][3], a23.y, w23.y);
        }
    }

    #pragma unroll
    for (int i = 0; i < 4; i++) {
        int r = rbase + ty * 4 + i;
        if (r >= N_NODES) continue;
        float2 p0 = u2f(acc[i][0]);
        float2 p1 = u2f(acc[i][1]);
        float2 p2 = u2f(acc[i][2]);
        float2 p3 = u2f(acc[i][3]);
        *(float4*)(y2b + (size_t)r * 128 + tx * 4) =
            make_float4(p0.x, p0.y, p1.x, p1.y);
        *(float4*)(y2b + (size_t)r * 128 + 64 + tx * 4) =
            make_float4(p2.x, p2.y, p3.x, p3.y);
    }
}

// ---------------- final gather + combine (layer 2) --------------------------
__global__ void __launch_bounds__(256) gather_kernel(const float* __restrict__ y2,
                                                     const float* __restrict__ bias,
                                                     float* __restrict__ outp) {
    int gw = (blockIdx.x * blockDim.x + threadIdx.x) >> 5;
    int lane = threadIdx.x & 31;
    if (gw >= N_NODES) return;

    int off = g_off[gw];
    int deg = g_deg[gw];
    int half = lane >> 4;
    int c4 = (lane & 15) << 2;
    const unsigned FULL = 0xffffffffu;

    float4 acc0 = make_float4(0.f, 0.f, 0.f, 0.f);
    float4 acc1 = make_float4(0.f, 0.f, 0.f, 0.f);

    for (int base = 0; base < deg; base += 32) {
        int n = min(32, deg - base);
        int sv = (lane < n) ? __ldg(&g_csr[off + base + lane]) : 0;
        int k = 0;
        for (; k + 4 <= n; k += 4) {
            int sa = __shfl_sync(FULL, sv, k + half);
            int sb = __shfl_sync(FULL, sv, k + 2 + half);
            float4 va = *(const float4*)(y2 + (size_t)sa * 128 + c4);
            float4 vb = *(const float4*)(y2 + (size_t)sb * 128 + c4);
            acc0.x += va.x; acc0.y += va.y; acc0.z += va.z; acc0.w += va.w;
            acc1.x += vb.x; acc1.y += vb.y; acc1.z += vb.z; acc1.w += vb.w;
        }
        if (k + 2 <= n) {
            int sa = __shfl_sync(FULL, sv, k + half);
            float4 va = *(const float4*)(y2 + (size_t)sa * 128 + c4);
            acc0.x += va.x; acc0.y += va.y; acc0.z += va.z; acc0.w += va.w;
            k += 2;
        }
        if (k < n) {
            int sa = __shfl_sync(FULL, sv, k);
            if (half == 0) {
                float4 va = *(const float4*)(y2 + (size_t)sa * 128 + c4);
                acc0.x += va.x; acc0.y += va.y; acc0.z += va.z; acc0.w += va.w;
            }
        }
    }

    float4 acc;
    acc.x = acc0.x + acc1.x;
    acc.y = acc0.y + acc1.y;
    acc.z = acc0.z + acc1.z;
    acc.w = acc0.w + acc1.w;
    acc.x += __shfl_down_sync(FULL, acc.x, 16);
    acc.y += __shfl_down_sync(FULL, acc.y, 16);
    acc.z += __shfl_down_sync(FULL, acc.z, 16);
    acc.w += __shfl_down_sync(FULL, acc.w, 16);

    if (half == 0) {
        float scale = 1.f / fmaxf((float)deg, 1.f);
        float4 z = *(const float4*)(y2 + (size_t)gw * 128 + 64 + c4);
        float4 b = *(const float4*)(bias + c4);
        float4 o;
        o.x = fmaxf(fmaf(acc.x, scale, z.x) + b.x, 0.f);
        o.y = fmaxf(fmaf(acc.y, scale, z.y) + b.y, 0.f);
        o.z = fmaxf(fmaf(acc.z, scale, z.z) + b.z, 0.f);
        o.w = fmaxf(fmaf(acc.w, scale, z.w) + b.w, 0.f);
        *(float4*)(outp + (size_t)gw * 64 + c4) = o;
    }
}

// ---------------- launch -----------------------------------------------------
extern "C" void kernel_launch(void* const* d_in, const int* in_sizes, int n_in,
                              void* d_out, int out_size) {
    const float* x   = (const float*)d_in[0];
    const int*   ei  = (const int*)d_in[1];
    const float* w1l = (const float*)d_in[2];
    const float* w1r = (const float*)d_in[3];
    const float* b1  = (const float*)d_in[4];
    const float* w2l = (const float*)d_in[5];
    const float* w2r = (const float*)d_in[6];
    const float* b2  = (const float*)d_in[7];
    const int* src = ei;             // edge_index[0, :]
    const int* dst = ei + N_EDGES;   // edge_index[1, :]
    float* out = (float*)d_out;

    const int FUSED_SMEM = (64 * 128 + 64 * 68 + 16 * 136) * 4;   // 58880 B

    static cudaStream_t s2 = nullptr;
    static cudaEvent_t e_fork = nullptr, e_join = nullptr;
    static float* y2_ptr = nullptr;
    static float* y2b_ptr = nullptr;
    if (!s2) {
        cudaStreamCreateWithFlags(&s2, cudaStreamNonBlocking);
        cudaEventCreateWithFlags(&e_fork, cudaEventDisableTiming);
        cudaEventCreateWithFlags(&e_join, cudaEventDisableTiming);
        cudaGetSymbolAddress((void**)&y2_ptr, g_y2);
        cudaGetSymbolAddress((void**)&y2b_ptr, g_y2b);
        cudaFuncSetAttribute(fused_kernel,
                             cudaFuncAttributeMaxDynamicSharedMemorySize,
                             FUSED_SMEM);
    }

    const int gemm_grid   = (N_NODES + 63) / 64;            // 782
    const int gather_grid = (N_NODES * 32 + 255) / 256;     // 6250
    const int edge_grid   = (N_EDGES + 255) / 256;

    // ---- fork: CSR build on s2, concurrent with gemm1 on main stream ----
    cudaEventRecord(e_fork, 0);
    cudaStreamWaitEvent(s2, e_fork, 0);

    zero_deg_kernel<<<NSB, SB, 0, s2>>>();
    hist_kernel<<<edge_grid, 256, 0, s2>>>(dst);
    scan_all_kernel<<<1, SCAN_T, 0, s2>>>();
    fill_kernel<<<edge_grid, 256, 0, s2>>>(src, dst);
    cudaEventRecord(e_join, s2);

    // main stream: layer-1 GEMM concurrent with CSR build
    gemm1_kernel<<<gemm_grid, 256>>>(x, w1l, w1r);          // g_y2 = x@[w1l|w1r]

    // ---- join, then fused gather1+gemm2, then final gather ----
    cudaStreamWaitEvent(0, e_join, 0);
    fused_kernel<<<gemm_grid, 256, FUSED_SMEM>>>(y2_ptr, b1, w2l, w2r, y2b_ptr);
    gather_kernel<<<gather_grid, 256>>>(y2b_ptr, b2, out);
}

// round 11
// speedup vs baseline: 1.0295x; 1.0295x over previous
#include <cuda_runtime.h>

#define N_NODES 50000
#define N_EDGES 800000
#define IN_CH 128
#define HID 64

// ---------------- scratch (static device globals: allocation-free) ----------
__device__ int   g_deg[N_NODES];
__device__ int   g_off[N_NODES];
__device__ int   g_woff[N_NODES];
__device__ int   g_csr[N_EDGES];
__device__ float g_y2[N_NODES * 128];   // [N][128]: cols 0:64 = A@Wl, 64:128 = A@Wr
__device__ float g_h[N_NODES * 64];

// ---------------- f32x2 helpers ---------------------------------------------
__device__ __forceinline__ void fma2(unsigned long long& d,
                                     unsigned long long a,
                                     unsigned long long b) {
    asm("fma.rn.f32x2 %0, %1, %2, %0;" : "+l"(d) : "l"(a), "l"(b));
}
__device__ __forceinline__ float2 u2f(unsigned long long v) {
    float2 r;
    asm("mov.b64 {%0, %1}, %2;" : "=f"(r.x), "=f"(r.y) : "l"(v));
    return r;
}

// ---------------- CSR build --------------------------------------------------
// hist: 4 edges per thread via int4 (N_EDGES % 4 == 0)
__global__ void hist_kernel(const int* __restrict__ dst) {
    int t = blockIdx.x * blockDim.x + threadIdx.x;
    int e4 = t * 4;
    if (e4 >= N_EDGES) return;
    int4 d = *(const int4*)(dst + e4);
    atomicAdd(&g_deg[d.x], 1);
    atomicAdd(&g_deg[d.y], 1);
    atomicAdd(&g_deg[d.z], 1);
    atomicAdd(&g_deg[d.w], 1);
}

// single-block full exclusive scan of g_deg -> g_off, g_woff (validated R10)
#define SCAN_T 1024
__global__ void __launch_bounds__(SCAN_T) scan_all_kernel() {
    __shared__ int warpsum[32];
    int t = threadIdx.x;
    int lane = t & 31, wid = t >> 5;
    const int CH = (N_NODES + SCAN_T - 1) / SCAN_T;   // 49
    int lo = t * CH;
    int hi = min(lo + CH, N_NODES);

    int local = 0;
    for (int i = lo; i < hi; i++) local += g_deg[i];

    int v = local;
    #pragma unroll
    for (int d = 1; d < 32; d <<= 1) {
        int u = __shfl_up_sync(0xffffffffu, v, d);
        if (lane >= d) v += u;
    }
    if (lane == 31) warpsum[wid] = v;
    __syncthreads();
    if (wid == 0) {
        int w = warpsum[lane];
        #pragma unroll
        for (int d = 1; d < 32; d <<= 1) {
            int u = __shfl_up_sync(0xffffffffu, w, d);
            if (lane >= d) w += u;
        }
        warpsum[lane] = w;
    }
    __syncthreads();

    int base = (v - local) + (wid ? warpsum[wid - 1] : 0);
    for (int i = lo; i < hi; i++) {
        g_off[i] = base;
        g_woff[i] = base;
        base += g_deg[i];
    }
}

// fill: 4 edges per thread via int4
__global__ void fill_kernel(const int* __restrict__ src,
                            const int* __restrict__ dst) {
    int t = blockIdx.x * blockDim.x + threadIdx.x;
    int e4 = t * 4;
    if (e4 >= N_EDGES) return;
    int4 s = *(const int4*)(src + e4);
    int4 d = *(const int4*)(dst + e4);
    g_csr[atomicAdd(&g_woff[d.x], 1)] = s.x;
    g_csr[atomicAdd(&g_woff[d.y], 1)] = s.y;
    g_csr[atomicAdd(&g_woff[d.z], 1)] = s.z;
    g_csr[atomicAdd(&g_woff[d.w], 1)] = s.w;
}

// ---------------- merged GEMM: g_y2[N,128] = A[N,K] @ [Wl | Wr] -------------
// (R9-validated)
template<int K, int ASEL>
__global__ void __launch_bounds__(256) gemm2_kernel(const float* __restrict__ Aext,
                                                    const float* __restrict__ Wl,
                                                    const float* __restrict__ Wr) {
    const float* A = (ASEL == 1) ? (const float*)g_h : Aext;

    __shared__ float Ws[64][128];
    __shared__ float Asd[16][136];

    int tid = threadIdx.x;
    int tx = tid & 15;
    int ty = tid >> 4;
    int rbase = blockIdx.x * 64;

    unsigned long long acc[4][4] = {};
    int ar = tid >> 2;
    int ak4 = (tid & 3) << 2;

    for (int kc = 0; kc < K; kc += 64) {
        for (int ks = 0; ks < 64; ks += 16) {
            if (ks == 0) {
                #pragma unroll
                for (int i = 0; i < 8; i++) {
                    int li = tid + i * 256;
                    int wk = li >> 5;
                    int wc4 = (li & 31) << 2;
                    const float* srcp = (wc4 < 64)
                        ? (Wl + (size_t)(kc + wk) * 64 + wc4)
                        : (Wr + (size_t)(kc + wk) * 64 + (wc4 - 64));
                    *(float4*)&Ws[wk][wc4] = *(const float4*)srcp;
                }
            }
            {
                int gr = rbase + ar;
                float4 a = make_float4(0.f, 0.f, 0.f, 0.f);
                if (gr < N_NODES)
                    a = *(const float4*)(A + (size_t)gr * K + kc + ks + ak4);
                *(float2*)&Asd[ak4 + 0][2 * ar] = make_float2(a.x, a.x);
                *(float2*)&Asd[ak4 + 1][2 * ar] = make_float2(a.y, a.y);
                *(float2*)&Asd[ak4 + 2][2 * ar] = make_float2(a.z, a.z);
                *(float2*)&Asd[ak4 + 3][2 * ar] = make_float2(a.w, a.w);
            }
            __syncthreads();

            #pragma unroll
            for (int k = 0; k < 16; k++) {
                ulonglong2 a01 = *(const ulonglong2*)&Asd[k][ty * 8];
                ulonglong2 a23 = *(const ulonglong2*)&Asd[k][ty * 8 + 4];
                ulonglong2 w01 = *(const ulonglong2*)&Ws[ks + k][tx * 4];
                ulonglong2 w23 = *(const ulonglong2*)&Ws[ks + k][64 + tx * 4];
                fma2(acc[0][0], a01.x, w01.x); fma2(acc[0][1], a01.x, w01.y);
                fma2(acc[0][2], a01.x, w23.x); fma2(acc[0][3], a01.x, w23.y);
                fma2(acc[1][0], a01.y, w01.x); fma2(acc[1][1], a01.y, w01.y);
                fma2(acc[1][2], a01.y, w23.x); fma2(acc[1][3], a01.y, w23.y);
                fma2(acc[2][0], a23.x, w01.x); fma2(acc[2][1], a23.x, w01.y);
                fma2(acc[2][2], a23.x, w23.x); fma2(acc[2][3], a23.x, w23.y);
                fma2(acc[3][0], a23.y, w01.x); fma2(acc[3][1], a23.y, w01.y);
                fma2(acc[3][2], a23.y, w23.x); fma2(acc[3][3], a23.y, w23.y);
            }
            __syncthreads();
        }
    }

    #pragma unroll
    for (int i = 0; i < 4; i++) {
        int r = rbase + ty * 4 + i;
        if (r >= N_NODES) continue;
        float2 p0 = u2f(acc[i][0]);
        float2 p1 = u2f(acc[i][1]);
        float2 p2 = u2f(acc[i][2]);
        float2 p3 = u2f(acc[i][3]);
        *(float4*)(g_y2 + (size_t)r * 128 + tx * 4) =
            make_float4(p0.x, p0.y, p1.x, p1.y);
        *(float4*)(g_y2 + (size_t)r * 128 + 64 + tx * 4) =
            make_float4(p2.x, p2.y, p3.x, p3.y);
    }
}

// ---------------- gather + combine (R9-validated) ----------------------------
__global__ void __launch_bounds__(256) gather_kernel(const float* __restrict__ bias,
                                                     float* __restrict__ outp) {
    int gw = (blockIdx.x * blockDim.x + threadIdx.x) >> 5;
    int lane = threadIdx.x & 31;
    if (gw >= N_NODES) return;

    int off = g_off[gw];
    int deg = g_deg[gw];
    int half = lane >> 4;
    int c4 = (lane & 15) << 2;
    const unsigned FULL = 0xffffffffu;

    float4 acc0 = make_float4(0.f, 0.f, 0.f, 0.f);
    float4 acc1 = make_float4(0.f, 0.f, 0.f, 0.f);

    for (int base = 0; base < deg; base += 32) {
        int n = min(32, deg - base);
        int sv = (lane < n) ? __ldg(&g_csr[off + base + lane]) : 0;
        int k = 0;
        for (; k + 4 <= n; k += 4) {
            int sa = __shfl_sync(FULL, sv, k + half);
            int sb = __shfl_sync(FULL, sv, k + 2 + half);
            float4 va = *(const float4*)(g_y2 + (size_t)sa * 128 + c4);
            float4 vb = *(const float4*)(g_y2 + (size_t)sb * 128 + c4);
            acc0.x += va.x; acc0.y += va.y; acc0.z += va.z; acc0.w += va.w;
            acc1.x += vb.x; acc1.y += vb.y; acc1.z += vb.z; acc1.w += vb.w;
        }
        if (k + 2 <= n) {
            int sa = __shfl_sync(FULL, sv, k + half);
            float4 va = *(const float4*)(g_y2 + (size_t)sa * 128 + c4);
            acc0.x += va.x; acc0.y += va.y; acc0.z += va.z; acc0.w += va.w;
            k += 2;
        }
        if (k < n) {
            int sa = __shfl_sync(FULL, sv, k);
            if (half == 0) {
                float4 va = *(const float4*)(g_y2 + (size_t)sa * 128 + c4);
                acc0.x += va.x; acc0.y += va.y; acc0.z += va.z; acc0.w += va.w;
            }
        }
    }

    float4 acc;
    acc.x = acc0.x + acc1.x;
    acc.y = acc0.y + acc1.y;
    acc.z = acc0.z + acc1.z;
    acc.w = acc0.w + acc1.w;
    acc.x += __shfl_down_sync(FULL, acc.x, 16);
    acc.y += __shfl_down_sync(FULL, acc.y, 16);
    acc.z += __shfl_down_sync(FULL, acc.z, 16);
    acc.w += __shfl_down_sync(FULL, acc.w, 16);

    if (half == 0) {
        float scale = 1.f / fmaxf((float)deg, 1.f);
        float4 z = *(const float4*)(g_y2 + (size_t)gw * 128 + 64 + c4);
        float4 b = *(const float4*)(bias + c4);
        float4 o;
        o.x = fmaxf(fmaf(acc.x, scale, z.x) + b.x, 0.f);
        o.y = fmaxf(fmaf(acc.y, scale, z.y) + b.y, 0.f);
        o.z = fmaxf(fmaf(acc.z, scale, z.z) + b.z, 0.f);
        o.w = fmaxf(fmaf(acc.w, scale, z.w) + b.w, 0.f);
        *(float4*)(outp + (size_t)gw * 64 + c4) = o;
    }
}

// ---------------- launch -----------------------------------------------------
extern "C" void kernel_launch(void* const* d_in, const int* in_sizes, int n_in,
                              void* d_out, int out_size) {
    const float* x   = (const float*)d_in[0];
    const int*   ei  = (const int*)d_in[1];
    const float* w1l = (const float*)d_in[2];
    const float* w1r = (const float*)d_in[3];
    const float* b1  = (const float*)d_in[4];
    const float* w2l = (const float*)d_in[5];
    const float* w2r = (const float*)d_in[6];
    const float* b2  = (const float*)d_in[7];
    const int* src = ei;             // edge_index[0, :]
    const int* dst = ei + N_EDGES;   // edge_index[1, :]
    float* out = (float*)d_out;

    static cudaStream_t s2 = nullptr;
    static cudaEvent_t e_fork = nullptr, e_join = nullptr;
    static float* h_ptr = nullptr;
    static int* deg_ptr = nullptr;
    if (!s2) {
        cudaStreamCreateWithFlags(&s2, cudaStreamNonBlocking);
        cudaEventCreateWithFlags(&e_fork, cudaEventDisableTiming);
        cudaEventCreateWithFlags(&e_join, cudaEventDisableTiming);
        cudaGetSymbolAddress((void**)&h_ptr, g_h);
        cudaGetSymbolAddress((void**)&deg_ptr, g_deg);
    }

    const int gemm_grid   = (N_NODES + 63) / 64;            // 782
    const int gather_grid = (N_NODES * 32 + 255) / 256;     // 6250
    const int edge4_grid  = (N_EDGES / 4 + 255) / 256;      // 782

    // ---- fork: CSR build on s2, concurrent with gemm1 on main stream ----
    cudaEventRecord(e_fork, 0);
    cudaStreamWaitEvent(s2, e_fork, 0);

    cudaMemsetAsync(deg_ptr, 0, N_NODES * sizeof(int), s2);
    hist_kernel<<<edge4_grid, 256, 0, s2>>>(dst);
    scan_all_kernel<<<1, SCAN_T, 0, s2>>>();
    fill_kernel<<<edge4_grid, 256, 0, s2>>>(src, dst);
    cudaEventRecord(e_join, s2);

    // main stream: layer-1 GEMM concurrent with CSR build
    gemm2_kernel<IN_CH, 0><<<gemm_grid, 256>>>(x, w1l, w1r);   // g_y2 = x@[w1l|w1r]

    // ---- join: gather needs both CSR and g_y2 ----
    cudaStreamWaitEvent(0, e_join, 0);
    gather_kernel<<<gather_grid, 256>>>(b1, h_ptr);            // g_h = relu(...)

    // ---- layer 2 ----
    gemm2_kernel<HID, 1><<<gemm_grid, 256>>>(nullptr, w2l, w2r); // g_y2 = h@[w2l|w2r]
    gather_kernel<<<gather_grid, 256>>>(b2, out);                // out = relu(...)
}

// round 12
// speedup vs baseline: 1.5857x; 1.5402x over previous
#include <cuda_runtime.h>

#define N_NODES 50000
#define N_EDGES 800000
#define IN_CH 128
#define HID 64

#define SB 512
#define NSB ((N_NODES + SB - 1) / SB)   // 98

// ---------------- scratch (static device globals: allocation-free) ----------
__device__ int   g_deg[N_NODES];
__device__ int   g_off[N_NODES];
__device__ int   g_woff[N_NODES];
__device__ int   g_part[NSB];
__device__ int   g_csr[N_EDGES];
__device__ float g_y2[N_NODES * 128];   // [N][128]: cols 0:64 = A@Wl, 64:128 = A@Wr
__device__ float g_h[N_NODES * 64];

// ---------------- f32x2 helpers ---------------------------------------------
__device__ __forceinline__ void fma2(unsigned long long& d,
                                     unsigned long long a,
                                     unsigned long long b) {
    asm("fma.rn.f32x2 %0, %1, %2, %0;" : "+l"(d) : "l"(a), "l"(b));
}
__device__ __forceinline__ float2 u2f(unsigned long long v) {
    float2 r;
    asm("mov.b64 {%0, %1}, %2;" : "=f"(r.x), "=f"(r.y) : "l"(v));
    return r;
}

// ---------------- CSR build (EXACT R9 code — validated at 139.7us) ----------
__global__ void zero_deg_kernel() {
    int i = blockIdx.x * blockDim.x + threadIdx.x;
    if (i < N_NODES) g_deg[i] = 0;
}

__global__ void hist_kernel(const int* __restrict__ dst) {
    int e = blockIdx.x * blockDim.x + threadIdx.x;
    if (e < N_EDGES) atomicAdd(&g_deg[dst[e]], 1);
}

__global__ void scan1_kernel() {   // grid NSB, block SB: per-block exclusive scan
    __shared__ int s[SB];
    int t = threadIdx.x;
    int i = blockIdx.x * SB + t;
    int v = (i < N_NODES) ? g_deg[i] : 0;
    s[t] = v;
    __syncthreads();
    #pragma unroll
    for (int d = 1; d < SB; d <<= 1) {
        int add = (t >= d) ? s[t - d] : 0;
        __syncthreads();
        s[t] += add;
        __syncthreads();
    }
    if (i < N_NODES) g_off[i] = s[t] - v;
    if (t == SB - 1) g_part[blockIdx.x] = s[t];
}

__global__ void scan2_kernel() {   // 1 block, 128 threads: scan block totals
    __shared__ int s[128];
    int t = threadIdx.x;
    int v = (t < NSB) ? g_part[t] : 0;
    s[t] = v;
    __syncthreads();
    #pragma unroll
    for (int d = 1; d < 128; d <<= 1) {
        int add = (t >= d) ? s[t - d] : 0;
        __syncthreads();
        s[t] += add;
        __syncthreads();
    }
    if (t < NSB) g_part[t] = s[t] - v;
}

__global__ void scan3_kernel() {
    int i = blockIdx.x * SB + threadIdx.x;
    if (i < N_NODES) {
        int o = g_off[i] + g_part[blockIdx.x];
        g_off[i] = o;
        g_woff[i] = o;
    }
}

__global__ void fill_kernel(const int* __restrict__ src,
                            const int* __restrict__ dst) {
    int e = blockIdx.x * blockDim.x + threadIdx.x;
    if (e < N_EDGES) {
        int pos = atomicAdd(&g_woff[dst[e]], 1);
        g_csr[pos] = src[e];
    }
}

// ---------------- merged GEMM: g_y2[N,128] = A[N,K] @ [Wl | Wr] -------------
// 256 threads, 128 rows/block, per-thread 8 rows x 8 cols (8x4 f32x2 accs).
// Ws[64][128] (32KB): k-chunk x 128 cols, pitch 128 (validated layout).
// Asd[8][264] (8.25KB): k-subchunk x duplicated rows, pitch 264 == 8 mod 32
// (same bank structure as validated pitch-136 layout).
template<int K, int ASEL>
__global__ void __launch_bounds__(256) gemm2_kernel(const float* __restrict__ Aext,
                                                    const float* __restrict__ Wl,
                                                    const float* __restrict__ Wr) {
    const float* A = (ASEL == 1) ? (const float*)g_h : Aext;

    __shared__ float Ws[64][128];
    __shared__ float Asd[8][264];

    int tid = threadIdx.x;
    int tx = tid & 15;        // col group: cols tx*4..+3 of each 64-half
    int ty = tid >> 4;        // row group: rows ty*8..ty*8+7
    int rbase = blockIdx.x * 128;

    unsigned long long acc[8][4] = {};

    int ar = tid >> 1;        // Asd stage: row 0..127
    int ak4 = (tid & 1) << 2; // Asd stage: k offset 0 or 4

    for (int kc = 0; kc < K; kc += 64) {
        for (int ks = 0; ks < 64; ks += 8) {
            if (ks == 0) {
                // stage Ws[64][128] for this kc: 2048 float4 = 8 per thread
                #pragma unroll
                for (int i = 0; i < 8; i++) {
                    int li = tid + i * 256;
                    int wk = li >> 5;
                    int wc4 = (li & 31) << 2;
                    const float* srcp = (wc4 < 64)
                        ? (Wl + (size_t)(kc + wk) * 64 + wc4)
                        : (Wr + (size_t)(kc + wk) * 64 + (wc4 - 64));
                    *(float4*)&Ws[wk][wc4] = *(const float4*)srcp;
                }
            }
            // stage Asd[8][dup 256]: one float4 per thread
            {
                int gr = rbase + ar;
                float4 a = make_float4(0.f, 0.f, 0.f, 0.f);
                if (gr < N_NODES)
                    a = *(const float4*)(A + (size_t)gr * K + kc + ks + ak4);
                *(float2*)&Asd[ak4 + 0][2 * ar] = make_float2(a.x, a.x);
                *(float2*)&Asd[ak4 + 1][2 * ar] = make_float2(a.y, a.y);
                *(float2*)&Asd[ak4 + 2][2 * ar] = make_float2(a.z, a.z);
                *(float2*)&Asd[ak4 + 3][2 * ar] = make_float2(a.w, a.w);
            }
            __syncthreads();

            #pragma unroll
            for (int k = 0; k < 8; k++) {
                ulonglong2 a01 = *(const ulonglong2*)&Asd[k][ty * 16];
                ulonglong2 a23 = *(const ulonglong2*)&Asd[k][ty * 16 + 4];
                ulonglong2 a45 = *(const ulonglong2*)&Asd[k][ty * 16 + 8];
                ulonglong2 a67 = *(const ulonglong2*)&Asd[k][ty * 16 + 12];
                ulonglong2 w01 = *(const ulonglong2*)&Ws[ks + k][tx * 4];
                ulonglong2 w23 = *(const ulonglong2*)&Ws[ks + k][64 + tx * 4];
                fma2(acc[0][0], a01.x, w01.x); fma2(acc[0][1], a01.x, w01.y);
                fma2(acc[0][2], a01.x, w23.x); fma2(acc[0][3], a01.x, w23.y);
                fma2(acc[1][0], a01.y, w01.x); fma2(acc[1][1], a01.y, w01.y);
                fma2(acc[1][2], a01.y, w23.x); fma2(acc[1][3], a01.y, w23.y);
                fma2(acc[2][0], a23.x, w01.x); fma2(acc[2][1], a23.x, w01.y);
                fma2(acc[2][2], a23.x, w23.x); fma2(acc[2][3], a23.x, w23.y);
                fma2(acc[3][0], a23.y, w01.x); fma2(acc[3][1], a23.y, w01.y);
                fma2(acc[3][2], a23.y, w23.x); fma2(acc[3][3], a23.y, w23.y);
                fma2(acc[4][0], a45.x, w01.x); fma2(acc[4][1], a45.x, w01.y);
                fma2(acc[4][2], a45.x, w23.x); fma2(acc[4][3], a45.x, w23.y);
                fma2(acc[5][0], a45.y, w01.x); fma2(acc[5][1], a45.y, w01.y);
                fma2(acc[5][2], a45.y, w23.x); fma2(acc[5][3], a45.y, w23.y);
                fma2(acc[6][0], a67.x, w01.x); fma2(acc[6][1], a67.x, w01.y);
                fma2(acc[6][2], a67.x, w23.x); fma2(acc[6][3], a67.x, w23.y);
                fma2(acc[7][0], a67.y, w01.x); fma2(acc[7][1], a67.y, w01.y);
                fma2(acc[7][2], a67.y, w23.x); fma2(acc[7][3], a67.y, w23.y);
            }
            __syncthreads();
        }
    }

    #pragma unroll
    for (int i = 0; i < 8; i++) {
        int r = rbase + ty * 8 + i;
        if (r >= N_NODES) continue;
        float2 p0 = u2f(acc[i][0]);
        float2 p1 = u2f(acc[i][1]);
        float2 p2 = u2f(acc[i][2]);
        float2 p3 = u2f(acc[i][3]);
        *(float4*)(g_y2 + (size_t)r * 128 + tx * 4) =
            make_float4(p0.x, p0.y, p1.x, p1.y);
        *(float4*)(g_y2 + (size_t)r * 128 + 64 + tx * 4) =
            make_float4(p2.x, p2.y, p3.x, p3.y);
    }
}

// ---------------- gather + combine (EXACT R9 code) ---------------------------
__global__ void __launch_bounds__(256) gather_kernel(const float* __restrict__ bias,
                                                     float* __restrict__ outp) {
    int gw = (blockIdx.x * blockDim.x + threadIdx.x) >> 5;
    int lane = threadIdx.x & 31;
    if (gw >= N_NODES) return;

    int off = g_off[gw];
    int deg = g_deg[gw];
    int half = lane >> 4;
    int c4 = (lane & 15) << 2;
    const unsigned FULL = 0xffffffffu;

    float4 acc0 = make_float4(0.f, 0.f, 0.f, 0.f);
    float4 acc1 = make_float4(0.f, 0.f, 0.f, 0.f);

    for (int base = 0; base < deg; base += 32) {
        int n = min(32, deg - base);
        int sv = (lane < n) ? __ldg(&g_csr[off + base + lane]) : 0;
        int k = 0;
        for (; k + 4 <= n; k += 4) {
            int sa = __shfl_sync(FULL, sv, k + half);
            int sb = __shfl_sync(FULL, sv, k + 2 + half);
            float4 va = *(const float4*)(g_y2 + (size_t)sa * 128 + c4);
            float4 vb = *(const float4*)(g_y2 + (size_t)sb * 128 + c4);
            acc0.x += va.x; acc0.y += va.y; acc0.z += va.z; acc0.w += va.w;
            acc1.x += vb.x; acc1.y += vb.y; acc1.z += vb.z; acc1.w += vb.w;
        }
        if (k + 2 <= n) {
            int sa = __shfl_sync(FULL, sv, k + half);
            float4 va = *(const float4*)(g_y2 + (size_t)sa * 128 + c4);
            acc0.x += va.x; acc0.y += va.y; acc0.z += va.z; acc0.w += va.w;
            k += 2;
        }
        if (k < n) {
            int sa = __shfl_sync(FULL, sv, k);
            if (half == 0) {
                float4 va = *(const float4*)(g_y2 + (size_t)sa * 128 + c4);
                acc0.x += va.x; acc0.y += va.y; acc0.z += va.z; acc0.w += va.w;
            }
        }
    }

    float4 acc;
    acc.x = acc0.x + acc1.x;
    acc.y = acc0.y + acc1.y;
    acc.z = acc0.z + acc1.z;
    acc.w = acc0.w + acc1.w;
    acc.x += __shfl_down_sync(FULL, acc.x, 16);
    acc.y += __shfl_down_sync(FULL, acc.y, 16);
    acc.z += __shfl_down_sync(FULL, acc.z, 16);
    acc.w += __shfl_down_sync(FULL, acc.w, 16);

    if (half == 0) {
        float scale = 1.f / fmaxf((float)deg, 1.f);
        float4 z = *(const float4*)(g_y2 + (size_t)gw * 128 + 64 + c4);
        float4 b = *(const float4*)(bias + c4);
        float4 o;
        o.x = fmaxf(fmaf(acc.x, scale, z.x) + b.x, 0.f);
        o.y = fmaxf(fmaf(acc.y, scale, z.y) + b.y, 0.f);
        o.z = fmaxf(fmaf(acc.z, scale, z.z) + b.z, 0.f);
        o.w = fmaxf(fmaf(acc.w, scale, z.w) + b.w, 0.f);
        *(float4*)(outp + (size_t)gw * 64 + c4) = o;
    }
}

// ---------------- launch (R9 structure; gemm grid now 128 rows/block) --------
extern "C" void kernel_launch(void* const* d_in, const int* in_sizes, int n_in,
                              void* d_out, int out_size) {
    const float* x   = (const float*)d_in[0];
    const int*   ei  = (const int*)d_in[1];
    const float* w1l = (const float*)d_in[2];
    const float* w1r = (const float*)d_in[3];
    const float* b1  = (const float*)d_in[4];
    const float* w2l = (const float*)d_in[5];
    const float* w2r = (const float*)d_in[6];
    const float* b2  = (const float*)d_in[7];
    const int* src = ei;             // edge_index[0, :]
    const int* dst = ei + N_EDGES;   // edge_index[1, :]
    float* out = (float*)d_out;

    static cudaStream_t s2 = nullptr;
    static cudaEvent_t e_fork = nullptr, e_join = nullptr;
    static float* h_ptr = nullptr;
    if (!s2) {
        cudaStreamCreateWithFlags(&s2, cudaStreamNonBlocking);
        cudaEventCreateWithFlags(&e_fork, cudaEventDisableTiming);
        cudaEventCreateWithFlags(&e_join, cudaEventDisableTiming);
        cudaGetSymbolAddress((void**)&h_ptr, g_h);
    }

    const int gemm_grid   = (N_NODES + 127) / 128;          // 391
    const int gather_grid = (N_NODES * 32 + 255) / 256;     // 6250
    const int edge_grid   = (N_EDGES + 255) / 256;          // 3125

    // ---- fork: CSR build on s2, concurrent with gemm1 on main stream ----
    cudaEventRecord(e_fork, 0);
    cudaStreamWaitEvent(s2, e_fork, 0);

    zero_deg_kernel<<<NSB, SB, 0, s2>>>();
    hist_kernel<<<edge_grid, 256, 0, s2>>>(dst);
    scan1_kernel<<<NSB, SB, 0, s2>>>();
    scan2_kernel<<<1, 128, 0, s2>>>();
    scan3_kernel<<<NSB, SB, 0, s2>>>();
    fill_kernel<<<edge_grid, 256, 0, s2>>>(src, dst);
    cudaEventRecord(e_join, s2);

    // main stream: layer-1 GEMM concurrent with CSR build
    gemm2_kernel<IN_CH, 0><<<gemm_grid, 256>>>(x, w1l, w1r);   // g_y2 = x@[w1l|w1r]

    // ---- join: gather needs both CSR and g_y2 ----
    cudaStreamWaitEvent(0, e_join, 0);
    gather_kernel<<<gather_grid, 256>>>(b1, h_ptr);            // g_h = relu(...)

    // ---- layer 2 ----
    gemm2_kernel<HID, 1><<<gemm_grid, 256>>>(nullptr, w2l, w2r); // g_y2 = h@[w2l|w2r]
    gather_kernel<<<gather_grid, 256>>>(b2, out);                // out = relu(...)
}

// round 13
// speedup vs baseline: 1.7355x; 1.0945x over previous
#include <cuda_runtime.h>

#define N_NODES 50000
#define N_EDGES 800000
#define IN_CH 128
#define HID 64

#define SB 512
#define NSB ((N_NODES + SB - 1) / SB)   // 98

// ---------------- scratch (static device globals: allocation-free) ----------
__device__ int   g_deg[N_NODES];
__device__ int   g_off[N_NODES];
__device__ int   g_woff[N_NODES];
__device__ int   g_part[NSB];
__device__ int   g_csr[N_EDGES];
__device__ float g_y2[N_NODES * 128];   // [N][128]: cols 0:64 = A@Wl, 64:128 = A@Wr
__device__ float g_h[N_NODES * 64];

// ---------------- f32x2 helpers ---------------------------------------------
__device__ __forceinline__ void fma2(unsigned long long& d,
                                     unsigned long long a,
                                     unsigned long long b) {
    asm("fma.rn.f32x2 %0, %1, %2, %0;" : "+l"(d) : "l"(a), "l"(b));
}
__device__ __forceinline__ float2 u2f(unsigned long long v) {
    float2 r;
    asm("mov.b64 {%0, %1}, %2;" : "=f"(r.x), "=f"(r.y) : "l"(v));
    return r;
}

// ---------------- CSR build (EXACT R9 code — validated at 139.7us) ----------
__global__ void zero_deg_kernel() {
    int i = blockIdx.x * blockDim.x + threadIdx.x;
    if (i < N_NODES) g_deg[i] = 0;
}

__global__ void hist_kernel(const int* __restrict__ dst) {
    int e = blockIdx.x * blockDim.x + threadIdx.x;
    if (e < N_EDGES) atomicAdd(&g_deg[dst[e]], 1);
}

__global__ void scan1_kernel() {
    __shared__ int s[SB];
    int t = threadIdx.x;
    int i = blockIdx.x * SB + t;
    int v = (i < N_NODES) ? g_deg[i] : 0;
    s[t] = v;
    __syncthreads();
    #pragma unroll
    for (int d = 1; d < SB; d <<= 1) {
        int add = (t >= d) ? s[t - d] : 0;
        __syncthreads();
        s[t] += add;
        __syncthreads();
    }
    if (i < N_NODES) g_off[i] = s[t] - v;
    if (t == SB - 1) g_part[blockIdx.x] = s[t];
}

__global__ void scan2_kernel() {
    __shared__ int s[128];
    int t = threadIdx.x;
    int v = (t < NSB) ? g_part[t] : 0;
    s[t] = v;
    __syncthreads();
    #pragma unroll
    for (int d = 1; d < 128; d <<= 1) {
        int add = (t >= d) ? s[t - d] : 0;
        __syncthreads();
        s[t] += add;
        __syncthreads();
    }
    if (t < NSB) g_part[t] = s[t] - v;
}

__global__ void scan3_kernel() {
    int i = blockIdx.x * SB + threadIdx.x;
    if (i < N_NODES) {
        int o = g_off[i] + g_part[blockIdx.x];
        g_off[i] = o;
        g_woff[i] = o;
    }
}

__global__ void fill_kernel(const int* __restrict__ src,
                            const int* __restrict__ dst) {
    int e = blockIdx.x * blockDim.x + threadIdx.x;
    if (e < N_EDGES) {
        int pos = atomicAdd(&g_woff[dst[e]], 1);
        g_csr[pos] = src[e];
    }
}

// ---------------- merged GEMM: g_y2[N,128] = A[N,K] @ [Wl | Wr] -------------
// R9 4x4-f32x2 tile (validated), but k-chunk 32 instead of 64:
// Ws[32][128] = 16KB (was 32KB) -> block smem 24.7KB -> 8 blocks/SM (was 5),
// grid 782 fully resident in one wave. All layouts/indexing otherwise R9-exact.
template<int K, int ASEL>
__global__ void __launch_bounds__(256) gemm2_kernel(const float* __restrict__ Aext,
                                                    const float* __restrict__ Wl,
                                                    const float* __restrict__ Wr) {
    const float* A = (ASEL == 1) ? (const float*)g_h : Aext;

    __shared__ float Ws[32][128];
    __shared__ float Asd[16][136];

    int tid = threadIdx.x;
    int tx = tid & 15;        // col group
    int ty = tid >> 4;        // row group
    int rbase = blockIdx.x * 64;

    unsigned long long acc[4][4] = {};

    int ar = tid >> 2;        // Asd stage: row 0..63
    int ak4 = (tid & 3) << 2; // Asd stage: k offset 0,4,8,12

    for (int kc = 0; kc < K; kc += 32) {
        for (int ks = 0; ks < 32; ks += 16) {
            if (ks == 0) {
                // stage Ws[32][128] for this kc: 1024 float4 = 4 per thread
                #pragma unroll
                for (int i = 0; i < 4; i++) {
                    int li = tid + i * 256;
                    int wk = li >> 5;
                    int wc4 = (li & 31) << 2;
                    const float* srcp = (wc4 < 64)
                        ? (Wl + (size_t)(kc + wk) * 64 + wc4)
                        : (Wr + (size_t)(kc + wk) * 64 + (wc4 - 64));
                    *(float4*)&Ws[wk][wc4] = *(const float4*)srcp;
                }
            }
            // stage Asd[16][dup 128]: one float4 per thread
            {
                int gr = rbase + ar;
                float4 a = make_float4(0.f, 0.f, 0.f, 0.f);
                if (gr < N_NODES)
                    a = *(const float4*)(A + (size_t)gr * K + kc + ks + ak4);
                *(float2*)&Asd[ak4 + 0][2 * ar] = make_float2(a.x, a.x);
                *(float2*)&Asd[ak4 + 1][2 * ar] = make_float2(a.y, a.y);
                *(float2*)&Asd[ak4 + 2][2 * ar] = make_float2(a.z, a.z);
                *(float2*)&Asd[ak4 + 3][2 * ar] = make_float2(a.w, a.w);
            }
            __syncthreads();

            #pragma unroll
            for (int k = 0; k < 16; k++) {
                ulonglong2 a01 = *(const ulonglong2*)&Asd[k][ty * 8];
                ulonglong2 a23 = *(const ulonglong2*)&Asd[k][ty * 8 + 4];
                ulonglong2 w01 = *(const ulonglong2*)&Ws[ks + k][tx * 4];
                ulonglong2 w23 = *(const ulonglong2*)&Ws[ks + k][64 + tx * 4];
                fma2(acc[0][0], a01.x, w01.x); fma2(acc[0][1], a01.x, w01.y);
                fma2(acc[0][2], a01.x, w23.x); fma2(acc[0][3], a01.x, w23.y);
                fma2(acc[1][0], a01.y, w01.x); fma2(acc[1][1], a01.y, w01.y);
                fma2(acc[1][2], a01.y, w23.x); fma2(acc[1][3], a01.y, w23.y);
                fma2(acc[2][0], a23.x, w01.x); fma2(acc[2][1], a23.x, w01.y);
                fma2(acc[2][2], a23.x, w23.x); fma2(acc[2][3], a23.x, w23.y);
                fma2(acc[3][0], a23.y, w01.x); fma2(acc[3][1], a23.y, w01.y);
                fma2(acc[3][2], a23.y, w23.x); fma2(acc[3][3], a23.y, w23.y);
            }
            __syncthreads();
        }
    }

    #pragma unroll
    for (int i = 0; i < 4; i++) {
        int r = rbase + ty * 4 + i;
        if (r >= N_NODES) continue;
        float2 p0 = u2f(acc[i][0]);
        float2 p1 = u2f(acc[i][1]);
        float2 p2 = u2f(acc[i][2]);
        float2 p3 = u2f(acc[i][3]);
        *(float4*)(g_y2 + (size_t)r * 128 + tx * 4) =
            make_float4(p0.x, p0.y, p1.x, p1.y);
        *(float4*)(g_y2 + (size_t)r * 128 + 64 + tx * 4) =
            make_float4(p2.x, p2.y, p3.x, p3.y);
    }
}

// ---------------- gather + combine (EXACT R9 code) ---------------------------
__global__ void __launch_bounds__(256) gather_kernel(const float* __restrict__ bias,
                                                     float* __restrict__ outp) {
    int gw = (blockIdx.x * blockDim.x + threadIdx.x) >> 5;
    int lane = threadIdx.x & 31;
    if (gw >= N_NODES) return;

    int off = g_off[gw];
    int deg = g_deg[gw];
    int half = lane >> 4;
    int c4 = (lane & 15) << 2;
    const unsigned FULL = 0xffffffffu;

    float4 acc0 = make_float4(0.f, 0.f, 0.f, 0.f);
    float4 acc1 = make_float4(0.f, 0.f, 0.f, 0.f);

    for (int base = 0; base < deg; base += 32) {
        int n = min(32, deg - base);
        int sv = (lane < n) ? __ldg(&g_csr[off + base + lane]) : 0;
        int k = 0;
        for (; k + 4 <= n; k += 4) {
            int sa = __shfl_sync(FULL, sv, k + half);
            int sb = __shfl_sync(FULL, sv, k + 2 + half);
            float4 va = *(const float4*)(g_y2 + (size_t)sa * 128 + c4);
            float4 vb = *(const float4*)(g_y2 + (size_t)sb * 128 + c4);
            acc0.x += va.x; acc0.y += va.y; acc0.z += va.z; acc0.w += va.w;
            acc1.x += vb.x; acc1.y += vb.y; acc1.z += vb.z; acc1.w += vb.w;
        }
        if (k + 2 <= n) {
            int sa = __shfl_sync(FULL, sv, k + half);
            float4 va = *(const float4*)(g_y2 + (size_t)sa * 128 + c4);
            acc0.x += va.x; acc0.y += va.y; acc0.z += va.z; acc0.w += va.w;
            k += 2;
        }
        if (k < n) {
            int sa = __shfl_sync(FULL, sv, k);
            if (half == 0) {
                float4 va = *(const float4*)(g_y2 + (size_t)sa * 128 + c4);
                acc0.x += va.x; acc0.y += va.y; acc0.z += va.z; acc0.w += va.w;
            }
        }
    }

    float4 acc;
    acc.x = acc0.x + acc1.x;
    acc.y = acc0.y + acc1.y;
    acc.z = acc0.z + acc1.z;
    acc.w = acc0.w + acc1.w;
    acc.x += __shfl_down_sync(FULL, acc.x, 16);
    acc.y += __shfl_down_sync(FULL, acc.y, 16);
    acc.z += __shfl_down_sync(FULL, acc.z, 16);
    acc.w += __shfl_down_sync(FULL, acc.w, 16);

    if (half == 0) {
        float scale = 1.f / fmaxf((float)deg, 1.f);
        float4 z = *(const float4*)(g_y2 + (size_t)gw * 128 + 64 + c4);
        float4 b = *(const float4*)(bias + c4);
        float4 o;
        o.x = fmaxf(fmaf(acc.x, scale, z.x) + b.x, 0.f);
        o.y = fmaxf(fmaf(acc.y, scale, z.y) + b.y, 0.f);
        o.z = fmaxf(fmaf(acc.z, scale, z.z) + b.z, 0.f);
        o.w = fmaxf(fmaf(acc.w, scale, z.w) + b.w, 0.f);
        *(float4*)(outp + (size_t)gw * 64 + c4) = o;
    }
}

// ---------------- launch (EXACT R9 structure) --------------------------------
extern "C" void kernel_launch(void* const* d_in, const int* in_sizes, int n_in,
                              void* d_out, int out_size) {
    const float* x   = (const float*)d_in[0];
    const int*   ei  = (const int*)d_in[1];
    const float* w1l = (const float*)d_in[2];
    const float* w1r = (const float*)d_in[3];
    const float* b1  = (const float*)d_in[4];
    const float* w2l = (const float*)d_in[5];
    const float* w2r = (const float*)d_in[6];
    const float* b2  = (const float*)d_in[7];
    const int* src = ei;             // edge_index[0, :]
    const int* dst = ei + N_EDGES;   // edge_index[1, :]
    float* out = (float*)d_out;

    static cudaStream_t s2 = nullptr;
    static cudaEvent_t e_fork = nullptr, e_join = nullptr;
    static float* h_ptr = nullptr;
    if (!s2) {
        cudaStreamCreateWithFlags(&s2, cudaStreamNonBlocking);
        cudaEventCreateWithFlags(&e_fork, cudaEventDisableTiming);
        cudaEventCreateWithFlags(&e_join, cudaEventDisableTiming);
        cudaGetSymbolAddress((void**)&h_ptr, g_h);
    }

    const int gemm_grid   = (N_NODES + 63) / 64;            // 782
    const int gather_grid = (N_NODES * 32 + 255) / 256;     // 6250
    const int edge_grid   = (N_EDGES + 255) / 256;

    // ---- fork: CSR build on s2, concurrent with gemm1 on main stream ----
    cudaEventRecord(e_fork, 0);
    cudaStreamWaitEvent(s2, e_fork, 0);

    zero_deg_kernel<<<NSB, SB, 0, s2>>>();
    hist_kernel<<<edge_grid, 256, 0, s2>>>(dst);
    scan1_kernel<<<NSB, SB, 0, s2>>>();
    scan2_kernel<<<1, 128, 0, s2>>>();
    scan3_kernel<<<NSB, SB, 0, s2>>>();
    fill_kernel<<<edge_grid, 256, 0, s2>>>(src, dst);
    cudaEventRecord(e_join, s2);

    // main stream: layer-1 GEMM concurrent with CSR build
    gemm2_kernel<IN_CH, 0><<<gemm_grid, 256>>>(x, w1l, w1r);   // g_y2 = x@[w1l|w1r]

    // ---- join: gather needs both CSR and g_y2 ----
    cudaStreamWaitEvent(0, e_join, 0);
    gather_kernel<<<gather_grid, 256>>>(b1, h_ptr);            // g_h = relu(...)

    // ---- layer 2 ----
    gemm2_kernel<HID, 1><<<gemm_grid, 256>>>(nullptr, w2l, w2r); // g_y2 = h@[w2l|w2r]
    gather_kernel<<<gather_grid, 256>>>(b2, out);                // out = relu(...)
}

// round 14
// speedup vs baseline: 1.7910x; 1.0319x over previous
#include <cuda_runtime.h>

#define N_NODES 50000
#define N_EDGES 800000
#define IN_CH 128
#define HID 64

#define SB 512
#define NSB ((N_NODES + SB - 1) / SB)   // 98

// ---------------- scratch (static device globals: allocation-free) ----------
__device__ int   g_deg[N_NODES];
__device__ int   g_off[N_NODES];    // block-local exclusive prefix (scan1)
__device__ int   g_woff[N_NODES];   // same, consumed by fill's atomicAdd
__device__ int   g_part[NSB];       // exclusive block prefixes (scan2)
__device__ int   g_csr[N_EDGES];
__device__ float g_y2[N_NODES * 128];   // [N][128]: cols 0:64 = A@Wl, 64:128 = A@Wr
__device__ float g_h[N_NODES * 64];

// ---------------- f32x2 helpers ---------------------------------------------
__device__ __forceinline__ void fma2(unsigned long long& d,
                                     unsigned long long a,
                                     unsigned long long b) {
    asm("fma.rn.f32x2 %0, %1, %2, %0;" : "+l"(d) : "l"(a), "l"(b));
}
__device__ __forceinline__ float2 u2f(unsigned long long v) {
    float2 r;
    asm("mov.b64 {%0, %1}, %2;" : "=f"(r.x), "=f"(r.y) : "l"(v));
    return r;
}

// ---------------- CSR build (R9-validated, minus scan3) ----------------------
__global__ void zero_deg_kernel() {
    int i = blockIdx.x * blockDim.x + threadIdx.x;
    if (i < N_NODES) g_deg[i] = 0;
}

__global__ void hist_kernel(const int* __restrict__ dst) {
    int e = blockIdx.x * blockDim.x + threadIdx.x;
    if (e < N_EDGES) atomicAdd(&g_deg[dst[e]], 1);
}

__global__ void scan1_kernel() {   // per-block exclusive scan -> g_off, g_woff
    __shared__ int s[SB];
    int t = threadIdx.x;
    int i = blockIdx.x * SB + t;
    int v = (i < N_NODES) ? g_deg[i] : 0;
    s[t] = v;
    __syncthreads();
    #pragma unroll
    for (int d = 1; d < SB; d <<= 1) {
        int add = (t >= d) ? s[t - d] : 0;
        __syncthreads();
        s[t] += add;
        __syncthreads();
    }
    if (i < N_NODES) {
        int ex = s[t] - v;
        g_off[i] = ex;
        g_woff[i] = ex;
    }
    if (t == SB - 1) g_part[blockIdx.x] = s[t];
}

__global__ void scan2_kernel() {   // 1 block: exclusive scan of block totals
    __shared__ int s[128];
    int t = threadIdx.x;
    int v = (t < NSB) ? g_part[t] : 0;
    s[t] = v;
    __syncthreads();
    #pragma unroll
    for (int d = 1; d < 128; d <<= 1) {
        int add = (t >= d) ? s[t - d] : 0;
        __syncthreads();
        s[t] += add;
        __syncthreads();
    }
    if (t < NSB) g_part[t] = s[t] - v;
}

// fill adds the block prefix inline (scan3 folded away)
__global__ void fill_kernel(const int* __restrict__ src,
                            const int* __restrict__ dst) {
    int e = blockIdx.x * blockDim.x + threadIdx.x;
    if (e < N_EDGES) {
        int d = dst[e];
        int pos = atomicAdd(&g_woff[d], 1) + g_part[d >> 9];
        g_csr[pos] = src[e];
    }
}

// ---------------- merged GEMM (R13-validated, + PDL hooks) -------------------
template<int K, int ASEL>
__global__ void __launch_bounds__(256) gemm2_kernel(const float* __restrict__ Aext,
                                                    const float* __restrict__ Wl,
                                                    const float* __restrict__ Wr) {
    const float* A = (ASEL == 1) ? (const float*)g_h : Aext;

    __shared__ float Ws[32][128];
    __shared__ float Asd[16][136];

    int tid = threadIdx.x;
    int tx = tid & 15;
    int ty = tid >> 4;
    int rbase = blockIdx.x * 64;

    unsigned long long acc[4][4] = {};
    int ar = tid >> 2;
    int ak4 = (tid & 3) << 2;

    // layer-2 instance reads g_h written by the preceding gather (PDL primary)
    if (ASEL == 1) cudaGridDependencySynchronize();

    for (int kc = 0; kc < K; kc += 32) {
        for (int ks = 0; ks < 32; ks += 16) {
            if (ks == 0) {
                #pragma unroll
                for (int i = 0; i < 4; i++) {
                    int li = tid + i * 256;
                    int wk = li >> 5;
                    int wc4 = (li & 31) << 2;
                    const float* srcp = (wc4 < 64)
                        ? (Wl + (size_t)(kc + wk) * 64 + wc4)
                        : (Wr + (size_t)(kc + wk) * 64 + (wc4 - 64));
                    *(float4*)&Ws[wk][wc4] = *(const float4*)srcp;
                }
            }
            {
                int gr = rbase + ar;
                float4 a = make_float4(0.f, 0.f, 0.f, 0.f);
                if (gr < N_NODES)
                    a = *(const float4*)(A + (size_t)gr * K + kc + ks + ak4);
                *(float2*)&Asd[ak4 + 0][2 * ar] = make_float2(a.x, a.x);
                *(float2*)&Asd[ak4 + 1][2 * ar] = make_float2(a.y, a.y);
                *(float2*)&Asd[ak4 + 2][2 * ar] = make_float2(a.z, a.z);
                *(float2*)&Asd[ak4 + 3][2 * ar] = make_float2(a.w, a.w);
            }
            __syncthreads();

            #pragma unroll
            for (int k = 0; k < 16; k++) {
                ulonglong2 a01 = *(const ulonglong2*)&Asd[k][ty * 8];
                ulonglong2 a23 = *(const ulonglong2*)&Asd[k][ty * 8 + 4];
                ulonglong2 w01 = *(const ulonglong2*)&Ws[ks + k][tx * 4];
                ulonglong2 w23 = *(const ulonglong2*)&Ws[ks + k][64 + tx * 4];
                fma2(acc[0][0], a01.x, w01.x); fma2(acc[0][1], a01.x, w01.y);
                fma2(acc[0][2], a01.x, w23.x); fma2(acc[0][3], a01.x, w23.y);
                fma2(acc[1][0], a01.y, w01.x); fma2(acc[1][1], a01.y, w01.y);
                fma2(acc[1][2], a01.y, w23.x); fma2(acc[1][3], a01.y, w23.y);
                fma2(acc[2][0], a23.x, w01.x); fma2(acc[2][1], a23.x, w01.y);
                fma2(acc[2][2], a23.x, w23.x); fma2(acc[2][3], a23.x, w23.y);
                fma2(acc[3][0], a23.y, w01.x); fma2(acc[3][1], a23.y, w01.y);
                fma2(acc[3][2], a23.y, w23.x); fma2(acc[3][3], a23.y, w23.y);
            }
            __syncthreads();
        }
    }

    // let the dependent kernel start launching while we store the epilogue
    cudaTriggerProgrammaticLaunchCompletion();

    #pragma unroll
    for (int i = 0; i < 4; i++) {
        int r = rbase + ty * 4 + i;
        if (r >= N_NODES) continue;
        float2 p0 = u2f(acc[i][0]);
        float2 p1 = u2f(acc[i][1]);
        float2 p2 = u2f(acc[i][2]);
        float2 p3 = u2f(acc[i][3]);
        *(float4*)(g_y2 + (size_t)r * 128 + tx * 4) =
            make_float4(p0.x, p0.y, p1.x, p1.y);
        *(float4*)(g_y2 + (size_t)r * 128 + 64 + tx * 4) =
            make_float4(p2.x, p2.y, p3.x, p3.y);
    }
}

// ---------------- gather + combine (R9-validated, + PDL hooks) ---------------
__global__ void __launch_bounds__(256) gather_kernel(const float* __restrict__ bias,
                                                     float* __restrict__ outp) {
    int gw = (blockIdx.x * blockDim.x + threadIdx.x) >> 5;
    int lane = threadIdx.x & 31;
    if (gw >= N_NODES) {
        cudaGridDependencySynchronize();
        return;
    }

    // CSR arrays come from the side stream (event-ordered at launch): safe pre-sync
    int off = g_off[gw] + g_part[gw >> 9];
    int deg = g_deg[gw];
    int half = lane >> 4;
    int c4 = (lane & 15) << 2;
    const unsigned FULL = 0xffffffffu;

    // g_y2 is the PDL primary's output: sync before first use
    cudaGridDependencySynchronize();

    float4 acc0 = make_float4(0.f, 0.f, 0.f, 0.f);
    float4 acc1 = make_float4(0.f, 0.f, 0.f, 0.f);

    for (int base = 0; base < deg; base += 32) {
        int n = min(32, deg - base);
        int sv = (lane < n) ? __ldg(&g_csr[off + base + lane]) : 0;
        int k = 0;
        for (; k + 4 <= n; k += 4) {
            int sa = __shfl_sync(FULL, sv, k + half);
            int sb = __shfl_sync(FULL, sv, k + 2 + half);
            float4 va = *(const float4*)(g_y2 + (size_t)sa * 128 + c4);
            float4 vb = *(const float4*)(g_y2 + (size_t)sb * 128 + c4);
            acc0.x += va.x; acc0.y += va.y; acc0.z += va.z; acc0.w += va.w;
            acc1.x += vb.x; acc1.y += vb.y; acc1.z += vb.z; acc1.w += vb.w;
        }
        if (k + 2 <= n) {
            int sa = __shfl_sync(FULL, sv, k + half);
            float4 va = *(const float4*)(g_y2 + (size_t)sa * 128 + c4);
            acc0.x += va.x; acc0.y += va.y; acc0.z += va.z; acc0.w += va.w;
            k += 2;
        }
        if (k < n) {
            int sa = __shfl_sync(FULL, sv, k);
            if (half == 0) {
                float4 va = *(const float4*)(g_y2 + (size_t)sa * 128 + c4);
                acc0.x += va.x; acc0.y += va.y; acc0.z += va.z; acc0.w += va.w;
            }
        }
    }

    cudaTriggerProgrammaticLaunchCompletion();

    float4 acc;
    acc.x = acc0.x + acc1.x;
    acc.y = acc0.y + acc1.y;
    acc.z = acc0.z + acc1.z;
    acc.w = acc0.w + acc1.w;
    acc.x += __shfl_down_sync(FULL, acc.x, 16);
    acc.y += __shfl_down_sync(FULL, acc.y, 16);
    acc.z += __shfl_down_sync(FULL, acc.z, 16);
    acc.w += __shfl_down_sync(FULL, acc.w, 16);

    if (half == 0) {
        float scale = 1.f / fmaxf((float)deg, 1.f);
        float4 z = *(const float4*)(g_y2 + (size_t)gw * 128 + 64 + c4);
        float4 b = *(const float4*)(bias + c4);
        float4 o;
        o.x = fmaxf(fmaf(acc.x, scale, z.x) + b.x, 0.f);
        o.y = fmaxf(fmaf(acc.y, scale, z.y) + b.y, 0.f);
        o.z = fmaxf(fmaf(acc.z, scale, z.z) + b.z, 0.f);
        o.w = fmaxf(fmaf(acc.w, scale, z.w) + b.w, 0.f);
        *(float4*)(outp + (size_t)gw * 64 + c4) = o;
    }
}

// ---------------- launch -----------------------------------------------------
extern "C" void kernel_launch(void* const* d_in, const int* in_sizes, int n_in,
                              void* d_out, int out_size) {
    const float* x   = (const float*)d_in[0];
    const int*   ei  = (const int*)d_in[1];
    const float* w1l = (const float*)d_in[2];
    const float* w1r = (const float*)d_in[3];
    const float* b1  = (const float*)d_in[4];
    const float* w2l = (const float*)d_in[5];
    const float* w2r = (const float*)d_in[6];
    const float* b2  = (const float*)d_in[7];
    const int* src = ei;             // edge_index[0, :]
    const int* dst = ei + N_EDGES;   // edge_index[1, :]
    float* out = (float*)d_out;

    static cudaStream_t s2 = nullptr;
    static cudaEvent_t e_fork = nullptr, e_join = nullptr;
    static float* h_ptr = nullptr;
    if (!s2) {
        cudaStreamCreateWithFlags(&s2, cudaStreamNonBlocking);
        cudaEventCreateWithFlags(&e_fork, cudaEventDisableTiming);
        cudaEventCreateWithFlags(&e_join, cudaEventDisableTiming);
        cudaGetSymbolAddress((void**)&h_ptr, g_h);
    }

    const int gemm_grid   = (N_NODES + 63) / 64;            // 782
    const int gather_grid = (N_NODES * 32 + 255) / 256;     // 6250
    const int edge_grid   = (N_EDGES + 255) / 256;

    // ---- fork: CSR build on s2, concurrent with gemm1 on main stream ----
    cudaEventRecord(e_fork, 0);
    cudaStreamWaitEvent(s2, e_fork, 0);

    zero_deg_kernel<<<NSB, SB, 0, s2>>>();
    hist_kernel<<<edge_grid, 256, 0, s2>>>(dst);
    scan1_kernel<<<NSB, SB, 0, s2>>>();
    scan2_kernel<<<1, 128, 0, s2>>>();
    fill_kernel<<<edge_grid, 256, 0, s2>>>(src, dst);
    cudaEventRecord(e_join, s2);

    // PDL launch config for the three dependent main-stream kernels
    cudaLaunchAttribute pdl_attr[1];
    pdl_attr[0].id = cudaLaunchAttributeProgrammaticStreamSerialization;
    pdl_attr[0].val.programmaticStreamSerializationAllowed = 1;

    cudaLaunchConfig_t cfg_gather = {};
    cfg_gather.gridDim = dim3(gather_grid);
    cfg_gather.blockDim = dim3(256);
    cfg_gather.stream = 0;
    cfg_gather.attrs = pdl_attr;
    cfg_gather.numAttrs = 1;

    cudaLaunchConfig_t cfg_gemm = cfg_gather;
    cfg_gemm.gridDim = dim3(gemm_grid);

    // main stream: layer-1 GEMM concurrent with CSR build (no PDL: first kernel)
    gemm2_kernel<IN_CH, 0><<<gemm_grid, 256>>>(x, w1l, w1r);   // g_y2 = x@[w1l|w1r]

    // ---- join: gather needs both CSR and g_y2 ----
    cudaStreamWaitEvent(0, e_join, 0);
    cudaLaunchKernelEx(&cfg_gather, gather_kernel, b1, (float*)h_ptr);   // g_h

    // ---- layer 2 ----
    cudaLaunchKernelEx(&cfg_gemm, gemm2_kernel<HID, 1>,
                       (const float*)nullptr, w2l, w2r);                 // g_y2 = h@[w2l|w2r]
    cudaLaunchKernelEx(&cfg_gather, gather_kernel, b2, out);             // out
}